// round 11
// baseline (speedup 1.0000x reference)
#include <cuda_runtime.h>
#include <cuda_bf16.h>

// Problem constants (fixed by the reference setup_inputs)
#define BATCH   16
#define HW      512
#define MCOMP   200000
#define NSM     148            // B200/sm_100a SM count relevant to LUT placement
#define KWAVE   4              // blocks per SM-slot (all co-resident, one wave)
#define NBLOCKS (NSM * KWAVE)  // 592
#define NTHR    256

#define EPS_F   1e-10f
#define THR_F   1.1f            // 1.0 + DELTA

// Scratch: per-block partial sums + per-block batch id (written by partial kernel)
__device__ float2 g_part[NBLOCKS];
__device__ int    g_batch[NBLOCKS];

__device__ __forceinline__ void whdr_one(const float* __restrict__ img,
                                         const float2* __restrict__ c2,
                                         int m, float& ws, float& wm)
{
    const float2 p0 = c2[(size_t)m * 3 + 0];   // (x1, y1)
    const float2 p1 = c2[(size_t)m * 3 + 1];   // (x2, y2)
    const float2 p2 = c2[(size_t)m * 3 + 2];   // (darker, weight)

    const int x1 = (int)p0.x, y1 = (int)p0.y;
    const int x2 = (int)p1.x, y2 = (int)p1.y;
    const int darker = (int)p2.x;
    const float w = p2.y;

    const float r1 = __ldg(img + y1 * HW + x1);
    const float r2 = __ldg(img + y2 * HW + x2);

    // alg = 1 if r2/(r1+eps) > thr ; 2 if r1/(r2+eps) > thr ; else 0
    int alg = 0;
    if (r2 > THR_F * (r1 + EPS_F))      alg = 1;
    else if (r1 > THR_F * (r2 + EPS_F)) alg = 2;

    ws += w;
    if (alg != darker) wm += w;
}

// Deterministic largest-remainder apportionment of NSM slots to BATCH batches,
// proportional to n_b. Fills S[b] (slots per batch) and P[b] (prefix).
// n_b in [100000,200000) => share in [6,12], so S[b] >= 1 always.
__device__ __forceinline__ void apportion_slots(const int* __restrict__ n,
                                                int* __restrict__ S,
                                                int* __restrict__ P)
{
    long long total = 0;
    #pragma unroll
    for (int i = 0; i < BATCH; i++) total += n[i];

    long long rem[BATCH];
    int used = 0;
    #pragma unroll
    for (int i = 0; i < BATCH; i++) {
        const long long num = (long long)NSM * n[i];
        S[i]   = (int)(num / total);
        rem[i] = num - (long long)S[i] * total;
        used  += S[i];
    }
    // distribute leftover slots to largest remainders (tie: lower index)
    for (int extra = NSM - used; extra > 0; extra--) {
        int best = 0;
        long long bv = -1;
        #pragma unroll
        for (int i = 0; i < BATCH; i++) {
            if (rem[i] > bv) { bv = rem[i]; best = i; }
        }
        S[best]++;
        rem[best] = -2;   // consumed
    }
    int acc = 0;
    #pragma unroll
    for (int i = 0; i < BATCH; i++) { P[i] = acc; acc += S[i]; }
}

__global__ __launch_bounds__(NTHR)
void whdr_partial_kernel(const float* __restrict__ v_input,
                         const float* __restrict__ comparisons,
                         const int*   __restrict__ numComparisons)
{
    __shared__ int s_n[BATCH];
    __shared__ int s_S[BATCH];
    __shared__ int s_P[BATCH];

    const int tid  = threadIdx.x;
    const int lane = tid & 31;
    const int warp = tid >> 5;

    if (tid < BATCH) s_n[tid] = numComparisons[tid];
    __syncthreads();
    if (tid == 0) apportion_slots(s_n, s_S, s_P);
    __syncthreads();

    // Batch-affinity: slot = bid % 148 decides the SM (classic LUT placement),
    // so all KWAVE blocks of one slot are co-resident on one SM and share ONE
    // image in L1 (1MB working set instead of ~7MB of mixed batches).
    const int bid  = blockIdx.x;
    const int slot = bid % NSM;
    const int kk   = bid / NSM;

    int b = 0;
    #pragma unroll
    for (int i = 1; i < BATCH; i++) b += (slot >= s_P[i]);

    const int Sb = s_S[b];
    const int r  = slot - s_P[b];          // rank of this slot within batch b
    const int nb = s_n[b];
    const int nblk = Sb * KWAVE;           // total blocks working on batch b
    const int j    = kk * Sb + r;          // this block's index within batch b

    const int lo = (int)(((long long)j       * nb) / nblk);
    const int hi = (int)(((long long)(j + 1) * nb) / nblk);

    const float* __restrict__ img = v_input + (size_t)b * HW * HW;
    const float2* __restrict__ c2 =
        (const float2*)(comparisons + (size_t)b * MCOMP * 6);

    float ws0 = 0.0f, wm0 = 0.0f;
    float ws1 = 0.0f, wm1 = 0.0f;

    // Proven R2-style loop: plain evict-normal float2 loads, 2-way unrolled,
    // contiguous slice [lo, hi) of this batch's records.
    int m = lo + tid;
    for (; m + NTHR < hi; m += 2 * NTHR) {
        whdr_one(img, c2, m,        ws0, wm0);
        whdr_one(img, c2, m + NTHR, ws1, wm1);
    }
    if (m < hi) whdr_one(img, c2, m, ws0, wm0);

    float ws = ws0 + ws1;
    float wm = wm0 + wm1;

    // block reduction (8 warps)
    __shared__ float s_ws[NTHR / 32];
    __shared__ float s_wm[NTHR / 32];
    #pragma unroll
    for (int o = 16; o > 0; o >>= 1) {
        ws += __shfl_down_sync(0xFFFFFFFFu, ws, o);
        wm += __shfl_down_sync(0xFFFFFFFFu, wm, o);
    }
    if (lane == 0) { s_ws[warp] = ws; s_wm[warp] = wm; }
    __syncthreads();
    if (warp == 0) {
        ws = (lane < NTHR / 32) ? s_ws[lane] : 0.0f;
        wm = (lane < NTHR / 32) ? s_wm[lane] : 0.0f;
        #pragma unroll
        for (int o = 4; o > 0; o >>= 1) {
            ws += __shfl_down_sync(0xFFFFFFFFu, ws, o);
            wm += __shfl_down_sync(0xFFFFFFFFu, wm, o);
        }
        if (lane == 0) {
            g_part[bid]  = make_float2(ws, wm);
            g_batch[bid] = b;
        }
    }
}

// Final reduction: 16 warps, warp w owns batch w; kernel boundary is the sync.
__global__ __launch_bounds__(512)
void whdr_final_kernel(float* __restrict__ out)
{
    const int warp = threadIdx.x >> 5;   // batch index 0..15
    const int lane = threadIdx.x & 31;

    float ws = 0.0f, wm = 0.0f;
    for (int k = lane; k < NBLOCKS; k += 32) {
        if (g_batch[k] == warp) {
            const float2 p = g_part[k];
            ws += p.x;
            wm += p.y;
        }
    }
    #pragma unroll
    for (int o = 16; o > 0; o >>= 1) {
        ws += __shfl_down_sync(0xFFFFFFFFu, ws, o);
        wm += __shfl_down_sync(0xFFFFFFFFu, wm, o);
    }

    __shared__ float s_per[BATCH];
    if (lane == 0) s_per[warp] = wm / ws;
    __syncthreads();

    if (threadIdx.x == 0) {
        float s = 0.0f;
        #pragma unroll
        for (int i = 0; i < BATCH; i++) s += s_per[i];
        out[0] = s * (1.0f / BATCH);
    }
}

extern "C" void kernel_launch(void* const* d_in, const int* in_sizes, int n_in,
                              void* d_out, int out_size)
{
    const float* v_input        = (const float*)d_in[0];
    const float* comparisons    = (const float*)d_in[1];
    const int*   numComparisons = (const int*)  d_in[2];
    float* out = (float*)d_out;

    whdr_partial_kernel<<<NBLOCKS, NTHR>>>(v_input, comparisons, numComparisons);
    whdr_final_kernel<<<1, 512>>>(out);
}

// round 12
// speedup vs baseline: 1.2194x; 1.2194x over previous
#include <cuda_runtime.h>
#include <cuda_bf16.h>

// Problem constants (fixed by the reference setup_inputs)
#define BATCH   16
#define HW      512
#define MCOMP   200000
#define NSM     148            // B200/sm_100a SM count (classic LUT placement)
#define KWAVE   8              // blocks per SM-slot: 8 x 256 = 2048 thr = full occ
#define NBLOCKS (NSM * KWAVE)  // 1184
#define NTHR    256
#define PBMAX   160            // max blocks per batch (<= 19 slots * 8), padded

#define EPS_F   1e-10f
#define THR_F   1.1f            // 1.0 + DELTA

// Dense per-batch partial layout: g_part[b*PBMAX + j], j < nblk(b).
// Unwritten entries are never touched (static zero-init) -> contribute 0.
__device__ float2 g_part[BATCH * PBMAX];

__device__ __forceinline__ void whdr_one(const float* __restrict__ img,
                                         const float2* __restrict__ c2,
                                         int m, float& ws, float& wm)
{
    const float2 p0 = c2[(size_t)m * 3 + 0];   // (x1, y1)
    const float2 p1 = c2[(size_t)m * 3 + 1];   // (x2, y2)
    const float2 p2 = c2[(size_t)m * 3 + 2];   // (darker, weight)

    const int x1 = (int)p0.x, y1 = (int)p0.y;
    const int x2 = (int)p1.x, y2 = (int)p1.y;
    const int darker = (int)p2.x;
    const float w = p2.y;

    const float r1 = __ldg(img + y1 * HW + x1);
    const float r2 = __ldg(img + y2 * HW + x2);

    // alg = 1 if r2/(r1+eps) > thr ; 2 if r1/(r2+eps) > thr ; else 0
    int alg = 0;
    if (r2 > THR_F * (r1 + EPS_F))      alg = 1;
    else if (r1 > THR_F * (r2 + EPS_F)) alg = 2;

    ws += w;
    if (alg != darker) wm += w;
}

// Deterministic largest-remainder apportionment of NSM slots to BATCH batches,
// proportional to n_b. n_b in [100K,200K) => S[b] in [6,19].
__device__ __forceinline__ void apportion_slots(const int* __restrict__ n,
                                                int* __restrict__ S,
                                                int* __restrict__ P)
{
    long long total = 0;
    #pragma unroll
    for (int i = 0; i < BATCH; i++) total += n[i];

    long long rem[BATCH];
    int used = 0;
    #pragma unroll
    for (int i = 0; i < BATCH; i++) {
        const long long num = (long long)NSM * n[i];
        S[i]   = (int)(num / total);
        rem[i] = num - (long long)S[i] * total;
        used  += S[i];
    }
    for (int extra = NSM - used; extra > 0; extra--) {
        int best = 0;
        long long bv = -1;
        #pragma unroll
        for (int i = 0; i < BATCH; i++) {
            if (rem[i] > bv) { bv = rem[i]; best = i; }
        }
        S[best]++;
        rem[best] = -2;   // consumed
    }
    int acc = 0;
    #pragma unroll
    for (int i = 0; i < BATCH; i++) { P[i] = acc; acc += S[i]; }
}

__global__ __launch_bounds__(NTHR, 8)
void whdr_partial_kernel(const float* __restrict__ v_input,
                         const float* __restrict__ comparisons,
                         const int*   __restrict__ numComparisons)
{
    __shared__ int s_n[BATCH];
    __shared__ int s_S[BATCH];
    __shared__ int s_P[BATCH];

    const int tid  = threadIdx.x;
    const int lane = tid & 31;
    const int warp = tid >> 5;

    if (tid < BATCH) s_n[tid] = numComparisons[tid];
    __syncthreads();
    if (tid == 0) apportion_slots(s_n, s_S, s_P);
    __syncthreads();

    // Batch-affinity: slot = bid % 148 decides the SM (classic LUT placement),
    // so all KWAVE=8 blocks of one slot are co-resident on one SM and share
    // ONE image in L1. Full occupancy: 2048 threads/SM hides gather latency.
    const int bid  = blockIdx.x;
    const int slot = bid % NSM;
    const int kk   = bid / NSM;          // 0..7

    int b = 0;
    #pragma unroll
    for (int i = 1; i < BATCH; i++) b += (slot >= s_P[i]);

    const int Sb   = s_S[b];
    const int r    = slot - s_P[b];      // rank of this slot within batch b
    const int nb   = s_n[b];
    const int nblk = Sb * KWAVE;         // total blocks working on batch b
    const int j    = kk * Sb + r;        // this block's index within batch b

    const int lo = (int)(((long long)j       * nb) / nblk);
    const int hi = (int)(((long long)(j + 1) * nb) / nblk);

    const float* __restrict__ img = v_input + (size_t)b * HW * HW;
    const float2* __restrict__ c2 =
        (const float2*)(comparisons + (size_t)b * MCOMP * 6);

    float ws0 = 0.0f, wm0 = 0.0f;
    float ws1 = 0.0f, wm1 = 0.0f;

    // Proven R2-style loop: plain evict-normal float2 loads, 2-way unrolled,
    // contiguous slice [lo, hi) of this batch's records.
    int m = lo + tid;
    for (; m + NTHR < hi; m += 2 * NTHR) {
        whdr_one(img, c2, m,        ws0, wm0);
        whdr_one(img, c2, m + NTHR, ws1, wm1);
    }
    if (m < hi) whdr_one(img, c2, m, ws0, wm0);

    float ws = ws0 + ws1;
    float wm = wm0 + wm1;

    // block reduction (8 warps)
    __shared__ float s_ws[NTHR / 32];
    __shared__ float s_wm[NTHR / 32];
    #pragma unroll
    for (int o = 16; o > 0; o >>= 1) {
        ws += __shfl_down_sync(0xFFFFFFFFu, ws, o);
        wm += __shfl_down_sync(0xFFFFFFFFu, wm, o);
    }
    if (lane == 0) { s_ws[warp] = ws; s_wm[warp] = wm; }
    __syncthreads();
    if (warp == 0) {
        ws = (lane < NTHR / 32) ? s_ws[lane] : 0.0f;
        wm = (lane < NTHR / 32) ? s_wm[lane] : 0.0f;
        #pragma unroll
        for (int o = 4; o > 0; o >>= 1) {
            ws += __shfl_down_sync(0xFFFFFFFFu, ws, o);
            wm += __shfl_down_sync(0xFFFFFFFFu, wm, o);
        }
        if (lane == 0) g_part[b * PBMAX + j] = make_float2(ws, wm);
    }
}

// Final reduction: 16 warps, warp b owns batch b. Dense fixed layout ->
// 5 independent coalesced loads per lane, no branches, no dependent chain.
__global__ __launch_bounds__(512)
void whdr_final_kernel(float* __restrict__ out)
{
    const int warp = threadIdx.x >> 5;   // batch index 0..15
    const int lane = threadIdx.x & 31;

    float ws = 0.0f, wm = 0.0f;
    #pragma unroll
    for (int k = 0; k < PBMAX / 32; k++) {
        const float2 p = g_part[warp * PBMAX + k * 32 + lane];
        ws += p.x;
        wm += p.y;
    }
    #pragma unroll
    for (int o = 16; o > 0; o >>= 1) {
        ws += __shfl_down_sync(0xFFFFFFFFu, ws, o);
        wm += __shfl_down_sync(0xFFFFFFFFu, wm, o);
    }

    __shared__ float s_per[BATCH];
    if (lane == 0) s_per[warp] = wm / ws;
    __syncthreads();

    if (threadIdx.x == 0) {
        float s = 0.0f;
        #pragma unroll
        for (int i = 0; i < BATCH; i++) s += s_per[i];
        out[0] = s * (1.0f / BATCH);
    }
}

extern "C" void kernel_launch(void* const* d_in, const int* in_sizes, int n_in,
                              void* d_out, int out_size)
{
    const float* v_input        = (const float*)d_in[0];
    const float* comparisons    = (const float*)d_in[1];
    const int*   numComparisons = (const int*)  d_in[2];
    float* out = (float*)d_out;

    whdr_partial_kernel<<<NBLOCKS, NTHR>>>(v_input, comparisons, numComparisons);
    whdr_final_kernel<<<1, 512>>>(out);
}

// round 13
// speedup vs baseline: 1.3567x; 1.1126x over previous
#include <cuda_runtime.h>
#include <cuda_bf16.h>
#include <cooperative_groups.h>

// Problem constants (fixed by the reference setup_inputs)
#define BATCH   16
#define HW      512
#define MCOMP   200000
#define NBLK    64
#define NTHR    256

#define EPS_F   1e-10f
#define THR_F   1.1f            // 1.0 + DELTA

// Scratch for per-block partial sums: (sum_w, sum_w*mismatch)
__device__ float2 g_part[BATCH * NBLK];

__device__ __forceinline__ void whdr_one(const float* __restrict__ img,
                                         const float2* __restrict__ c2,
                                         int m, float& ws, float& wm)
{
    const float2 p0 = c2[m * 3 + 0];   // (x1, y1)
    const float2 p1 = c2[m * 3 + 1];   // (x2, y2)
    const float2 p2 = c2[m * 3 + 2];   // (darker, weight)

    const int x1 = (int)p0.x, y1 = (int)p0.y;
    const int x2 = (int)p1.x, y2 = (int)p1.y;
    const int darker = (int)p2.x;
    const float w = p2.y;

    const float r1 = __ldg(img + y1 * HW + x1);
    const float r2 = __ldg(img + y2 * HW + x2);

    // alg = 1 if r2/(r1+eps) > thr ; 2 if r1/(r2+eps) > thr ; else 0
    // multiply-form (all values positive) avoids divides
    int alg = 0;
    if (r2 > THR_F * (r1 + EPS_F))      alg = 1;
    else if (r1 > THR_F * (r2 + EPS_F)) alg = 2;

    ws += w;
    if (alg != darker) wm += w;
}

// Exact R2 partial kernel — proven fastest mainloop (24.3us).
__global__ __launch_bounds__(NTHR)
void whdr_partial_kernel(const float* __restrict__ v_input,
                         const float* __restrict__ comparisons,
                         const int*   __restrict__ numComparisons)
{
    const int b   = blockIdx.y;
    const int blk = blockIdx.x;
    const float* __restrict__ img = v_input + (size_t)b * HW * HW;
    const float2* __restrict__ c2 =
        (const float2*)(comparisons + (size_t)b * MCOMP * 6);
    const int n = numComparisons[b];

    float ws0 = 0.0f, wm0 = 0.0f;
    float ws1 = 0.0f, wm1 = 0.0f;

    const int stride = NBLK * NTHR;
    int m = blk * NTHR + threadIdx.x;
    for (; m + stride < n; m += 2 * stride) {
        whdr_one(img, c2, m,          ws0, wm0);
        whdr_one(img, c2, m + stride, ws1, wm1);
    }
    if (m < n) whdr_one(img, c2, m, ws0, wm0);

    float ws = ws0 + ws1;
    float wm = wm0 + wm1;

    // block reduction (8 warps)
    __shared__ float s_ws[NTHR / 32];
    __shared__ float s_wm[NTHR / 32];
    const int lane = threadIdx.x & 31;
    const int warp = threadIdx.x >> 5;
    #pragma unroll
    for (int o = 16; o > 0; o >>= 1) {
        ws += __shfl_down_sync(0xFFFFFFFFu, ws, o);
        wm += __shfl_down_sync(0xFFFFFFFFu, wm, o);
    }
    if (lane == 0) { s_ws[warp] = ws; s_wm[warp] = wm; }
    __syncthreads();
    if (warp == 0) {
        ws = (lane < NTHR / 32) ? s_ws[lane] : 0.0f;
        wm = (lane < NTHR / 32) ? s_wm[lane] : 0.0f;
        #pragma unroll
        for (int o = 4; o > 0; o >>= 1) {
            ws += __shfl_down_sync(0xFFFFFFFFu, ws, o);
            wm += __shfl_down_sync(0xFFFFFFFFu, wm, o);
        }
        if (lane == 0) g_part[b * NBLK + blk] = make_float2(ws, wm);
    }
}

// Final reduction with PDL: this kernel is launched with
// programmaticStreamSerializationAllowed=1, so it begins (ramp, smem init,
// instruction fetch) WHILE the partial kernel's tail is still running, then
// cudaGridDependencySynchronize() blocks until the partial grid completes
// (implicit completion trigger at grid exit; memory visibility guaranteed).
__global__ __launch_bounds__(512)
void whdr_final_kernel(float* __restrict__ out)
{
#if __CUDA_ARCH__ >= 900
    cudaGridDependencySynchronize();
#endif

    const int warp = threadIdx.x >> 5;   // batch index, 0..15
    const int lane = threadIdx.x & 31;

    const float2 a = g_part[warp * NBLK + lane];
    const float2 c = g_part[warp * NBLK + 32 + lane];
    float ws = a.x + c.x;
    float wm = a.y + c.y;
    #pragma unroll
    for (int o = 16; o > 0; o >>= 1) {
        ws += __shfl_down_sync(0xFFFFFFFFu, ws, o);
        wm += __shfl_down_sync(0xFFFFFFFFu, wm, o);
    }

    __shared__ float s_per[BATCH];
    if (lane == 0) s_per[warp] = wm / ws;
    __syncthreads();

    if (threadIdx.x == 0) {
        float s = 0.0f;
        #pragma unroll
        for (int i = 0; i < BATCH; i++) s += s_per[i];
        out[0] = s * (1.0f / BATCH);
    }
}

extern "C" void kernel_launch(void* const* d_in, const int* in_sizes, int n_in,
                              void* d_out, int out_size)
{
    const float* v_input        = (const float*)d_in[0];
    const float* comparisons    = (const float*)d_in[1];
    const int*   numComparisons = (const int*)  d_in[2];
    float* out = (float*)d_out;

    dim3 grid(NBLK, BATCH, 1);
    whdr_partial_kernel<<<grid, NTHR>>>(v_input, comparisons, numComparisons);

    // PDL launch of the final reduction: overlap its launch/ramp with the
    // partial kernel's tail; cudaGridDependencySynchronize() inside provides
    // the ordering. Captured into the graph as a programmatic edge.
    cudaLaunchConfig_t cfg = {};
    cfg.gridDim  = dim3(1, 1, 1);
    cfg.blockDim = dim3(512, 1, 1);
    cfg.dynamicSmemBytes = 0;
    cfg.stream = 0;   // legacy default stream (the captured stream)

    cudaLaunchAttribute attrs[1];
    attrs[0].id = cudaLaunchAttributeProgrammaticStreamSerialization;
    attrs[0].val.programmaticStreamSerializationAllowed = 1;
    cfg.attrs    = attrs;
    cfg.numAttrs = 1;

    cudaLaunchKernelEx(&cfg, whdr_final_kernel, out);
}